// round 14
// baseline (speedup 1.0000x reference)
#include <cuda_runtime.h>
#include <math.h>

// ---------------------------------------------------------------------------
// Balanced Sinkhorn, persistent single-kernel, zero per-row FP64.
// E' = exp((f - colmax)/eps) in [0,1] (column shift exactly invariant: the
// reference row-normalizes first) lives entirely in shared memory.
// Per-row scalars factored as r = 1/c so all products stay in fp32 range.
// R14: pass bodies use packed fma.rn.f32x2 (sm_103a FFMA2; E rows loaded as
// ulonglong2 so packing is free), warp-0-only grid barrier (one fewer
// __syncthreads, earlier release stores), __fdividef preambles.
// ---------------------------------------------------------------------------

#define NB 16384
#define NK 256
#define GRID_P 148
#define BLOCK_P 512
#define WARPS_P 16
#define N_OUTER 10
#define INV_B 6.103515625e-05f   // 1/16384 (exact)
#define CHUNK 4
#define STRIDE (WARPS_P * CHUNK)   // 64
#define CHUNK2 2
#define STRIDE2 (WARPS_P * CHUNK2) // 32
#define GP  32   // accumulator pad: 32 doubles = 256 B per logical element
#define GPC 64   // cmax pad: 64 uints = 256 B

typedef unsigned long long u64;

// shared memory layout (bytes)
#define OFF_RED  0        // double[256]   2048
#define OFF_K2   2048     // double[256]   2048
#define OFF_R1   4096     // double[256]   2048
#define OFF_SCL  6144     // double[4]       64 (scalar broadcast)
#define OFF_W    6208     // float[256]    1024
#define OFF_BUF  7232     // float[256]    1024
#define OFF_V1   8256     // float[112]     448
#define OFF_V2   8704     // float[112]     448
#define OFF_U    9152     // float[256]    1024
#define OFF_ACC  10176    // float[16*256] 16384
#define OFF_E    26560    // float[111*256] 113664
#define SMEM_TOTAL 140224

// Global state (allocation-free). Barrier counter/flags monotonic across graph
// replays (uniform fixed barrier count per launch); accumulators re-zeroed
// inside the kernel each launch; cmax idempotent. All accumulators 256B-strided.
static __device__ unsigned g_count;                              // arrivals
static __device__ __align__(128) unsigned g_flag[GRID_P * 32];   // 128B-padded
static __device__ __align__(256) unsigned g_cmax[NK * GPC];
static __device__ __align__(256) double g_R1[NK * GP];
static __device__ __align__(256) double g_R2[2][NK * GP], g_R3[2][NK * GP];
static __device__ __align__(256) double g_ub1[2][NK * GP], g_ub2[2][NK * GP],
                                        g_ub3[2][NK * GP];

// ---- packed f32x2 primitives (sm_103a) ----
__device__ __forceinline__ u64 pk2(float lo, float hi) {
    u64 r; asm("mov.b64 %0,{%1,%2};" : "=l"(r) : "f"(lo), "f"(hi)); return r;
}
__device__ __forceinline__ void upk2(u64 p, float& lo, float& hi) {
    asm("mov.b64 {%0,%1},%2;" : "=f"(lo), "=f"(hi) : "l"(p));
}
__device__ __forceinline__ u64 fma2(u64 a, u64 b, u64 c) {
    u64 d; asm("fma.rn.f32x2 %0,%1,%2,%3;" : "=l"(d) : "l"(a), "l"(b), "l"(c));
    return d;
}
__device__ __forceinline__ u64 mul2(u64 a, u64 b) {
    u64 d; asm("mul.rn.f32x2 %0,%1,%2;" : "=l"(d) : "l"(a), "l"(b)); return d;
}
__device__ __forceinline__ u64 add2(u64 a, u64 b) {
    u64 d; asm("add.rn.f32x2 %0,%1,%2;" : "=l"(d) : "l"(a), "l"(b)); return d;
}
// packed dot over 4 pairs -> scalar
__device__ __forceinline__ float dot8p(const u64 E[4], const u64 U[4]) {
    u64 d = mul2(E[3], U[3]);
    d = fma2(E[2], U[2], d);
    d = fma2(E[1], U[1], d);
    d = fma2(E[0], U[0], d);
    float lo, hi; upk2(d, lo, hi);
    return lo + hi;
}

__device__ __forceinline__ float frcp(float x) {
    float r; asm("rcp.approx.f32 %0, %1;" : "=f"(r) : "f"(x)); return r;
}
// fp32-seeded double reciprocal with one DP Newton step (~2^-46)
__device__ __forceinline__ double rcpd(double x) {
    double r = (double)frcp((float)x);
    return r * (2.0 - x * r);
}
__device__ __forceinline__ unsigned encf(float x) {
    unsigned u = __float_as_uint(x);
    return (u & 0x80000000u) ? ~u : (u | 0x80000000u);
}
__device__ __forceinline__ float decf(unsigned e) {
    unsigned u = (e & 0x80000000u) ? (e & 0x7fffffffu) : ~e;
    return __uint_as_float(u);
}

__device__ __forceinline__ double warpRedSumD(double v) {
#pragma unroll
    for (int m = 16; m; m >>= 1) v += __shfl_xor_sync(0xffffffffu, v, m);
    return v;
}
__device__ __forceinline__ float warpRedMaxF(float v) {
#pragma unroll
    for (int m = 16; m; m >>= 1) v = fmaxf(v, __shfl_xor_sync(0xffffffffu, v, m));
    return v;
}

// interleaved butterflies (pipeline SHFL latency across independent rows)
__device__ __forceinline__ void bflyN(float* c, int n) {
#pragma unroll
    for (int m = 16; m; m >>= 1)
        for (int i = 0; i < n; i++)
            c[i] += __shfl_xor_sync(0xffffffffu, c[i], m);
}

// ---------------------------------------------------------------------------
// Grid barrier, warp-0-only protocol:
//  lane0 arrival acq_rel RMW on g_count; t broadcast via shfl (no smem, no
//  extra syncthreads); if releaser, warp 0's lanes st.release all per-block
//  flags (stride 32); lane0 acquire-polls this block's OWN flag.
// Monotonic epochs: old/GRID+1, poll >=. Safe across graph replays.
// ---------------------------------------------------------------------------
__device__ __forceinline__ void gridBar(int tid, int bid) {
    __syncthreads();
    if (tid < 32) {
        unsigned t = 0;
        if (tid == 0)
            asm volatile("atom.acq_rel.gpu.global.add.u32 %0, [%1], 1;"
                         : "=r"(t) : "l"(&g_count) : "memory");
        t = __shfl_sync(0xffffffffu, t, 0);
        unsigned epoch = t / GRID_P + 1u;
        if ((t % GRID_P) == GRID_P - 1u) {      // this block is the releaser
            for (int b = tid; b < GRID_P; b += 32)
                asm volatile("st.release.gpu.global.u32 [%0], %1;"
                             :: "l"(&g_flag[b * 32]), "r"(epoch) : "memory");
        }
        if (tid == 0) {
            unsigned v;
            do {
                asm volatile("ld.acquire.gpu.global.u32 %0, [%1];"
                             : "=r"(v) : "l"(&g_flag[bid * 32]) : "memory");
            } while (v < epoch);
        }
    }
    __syncthreads();
}

// packed per-warp partials -> block fp32 -> global fp64 atomic (256B-strided)
__device__ __forceinline__ void blockAcc(float* sacc, const u64 A[4],
                                         int lane, int warp, int tid,
                                         double* gdst) {
    float a[8];
    upk2(A[0], a[0], a[1]); upk2(A[1], a[2], a[3]);
    upk2(A[2], a[4], a[5]); upk2(A[3], a[6], a[7]);
    float4* dst = (float4*)(sacc + warp * NK);
    dst[lane]      = make_float4(a[0], a[1], a[2], a[3]);
    dst[32 + lane] = make_float4(a[4], a[5], a[6], a[7]);
    __syncthreads();
    if (tid < NK) {
        float s = 0.f;
#pragma unroll
        for (int w = 0; w < WARPS_P; w++) s += sacc[w * NK + tid];
        atomicAdd(&gdst[tid * GP], (double)s);
    }
}

__device__ __forceinline__ void loadU(const float* su, int lane, u64 U[4]) {
    const ulonglong2* up = (const ulonglong2*)su;
    ulonglong2 q0 = up[lane], q1 = up[32 + lane];
    U[0] = q0.x; U[1] = q0.y; U[2] = q1.x; U[3] = q1.y;
}
__device__ __forceinline__ void loadE(const float* sE, int lr, int lane, u64 E[4]) {
    const ulonglong2* row = (const ulonglong2*)(sE + lr * NK);
    ulonglong2 p0 = row[lane], p1 = row[32 + lane];
    E[0] = p0.x; E[1] = p0.y; E[2] = p1.x; E[3] = p1.y;
}

// fwd: c[b]=sum u*E; r=1/c stored; Rout[k] += E*(r/B). Packed math.
__device__ __forceinline__ void fwdBody(const float* sE, const float* su,
                                        float* svf, int nrows, double* Rout,
                                        float* sacc, int lane, int warp, int tid) {
    u64 U[4]; loadU(su, lane, U);
    u64 A[4] = {0, 0, 0, 0};
    for (int lr0 = warp * CHUNK; lr0 < nrows; lr0 += STRIDE) {
        u64 E[CHUNK][4];
        float c[CHUNK];
#pragma unroll
        for (int i = 0; i < CHUNK; i++) {
            if (lr0 + i < nrows) {
                loadE(sE, lr0 + i, lane, E[i]);
                c[i] = dot8p(E[i], U);
            } else {
                E[i][0] = E[i][1] = E[i][2] = E[i][3] = 0ull; c[i] = 1.f;
            }
        }
        bflyN(c, CHUNK);
#pragma unroll
        for (int i = 0; i < CHUNK; i++) {
            float r = frcp(fmaxf(c[i], 1e-37f));
            if (lane == 0 && lr0 + i < nrows) svf[lr0 + i] = r;
            float vf = r * INV_B;
            u64 V2 = pk2(vf, vf);
#pragma unroll
            for (int j = 0; j < 4; j++) A[j] = fma2(E[i][j], V2, A[j]);
        }
    }
    blockAcc(sacc, A, lane, warp, tid, Rout);
}

// passC (3rd fwd fused with bwd layer 3), packed:
//  c, s = sum u*E{,*P}; r=1/c; v3=r/B; cbar=(s*r)*v3; ub3 += E*(cbar - v3*P)
__device__ __forceinline__ void passCBody(const float* sE, const float* su,
                                          const float* __restrict__ fin, int rs,
                                          int nrows, double* gdst, float* sacc,
                                          int lane, int warp, int tid) {
    u64 U[4]; loadU(su, lane, U);
    u64 A[4] = {0, 0, 0, 0};
    for (int lr0 = warp * CHUNK2; lr0 < nrows; lr0 += STRIDE2) {
        u64 E[CHUNK2][4], P[CHUNK2][4];
        float c[CHUNK2], s[CHUNK2];
#pragma unroll
        for (int i = 0; i < CHUNK2; i++) {
            if (lr0 + i < nrows) {
                loadE(sE, lr0 + i, lane, E[i]);
                const ulonglong2* frow =
                    (const ulonglong2*)(fin + (size_t)(rs + lr0 + i) * NK);
                ulonglong2 f0 = frow[lane], f1 = frow[32 + lane];
                P[i][0] = f0.x; P[i][1] = f0.y; P[i][2] = f1.x; P[i][3] = f1.y;
                u64 tc[4];
#pragma unroll
                for (int j = 0; j < 4; j++) tc[j] = mul2(E[i][j], U[j]);
                u64 cs = add2(add2(tc[0], tc[1]), add2(tc[2], tc[3]));
                u64 ss = fma2(tc[0], P[i][0],
                          fma2(tc[1], P[i][1],
                           fma2(tc[2], P[i][2], mul2(tc[3], P[i][3]))));
                float lo, hi;
                upk2(cs, lo, hi); c[i] = lo + hi;
                upk2(ss, lo, hi); s[i] = lo + hi;
            } else {
                E[i][0]=E[i][1]=E[i][2]=E[i][3]=0ull;
                P[i][0]=P[i][1]=P[i][2]=P[i][3]=0ull;
                c[i] = 1.f; s[i] = 0.f;
            }
        }
        bflyN(c, CHUNK2);
        bflyN(s, CHUNK2);
#pragma unroll
        for (int i = 0; i < CHUNK2; i++) {
            float r = frcp(fmaxf(c[i], 1e-37f));
            float v3f = r * INV_B;
            float cbf = (s[i] * r) * v3f;     // = B*v3^2*s, overflow-safe order
            u64 NV2 = pk2(-v3f, -v3f);
            u64 CB2 = pk2(cbf, cbf);
#pragma unroll
            for (int j = 0; j < 4; j++) {
                u64 t = fma2(P[i][j], NV2, CB2);   // cbf - v3f*P
                A[j] = fma2(E[i][j], t, A[j]);
            }
        }
    }
    blockAcc(sacc, A, lane, warp, tid, gdst);
}

// bwd layer: t[b]=sum rb*E; cb=-(t*r)*(r/B); ub_out += E*cb. Packed.
__device__ __forceinline__ void bwdBody(const float* sE, const float* su,
                                        const float* svf, int nrows, double* gdst,
                                        float* sacc, int lane, int warp, int tid) {
    u64 U[4]; loadU(su, lane, U);
    u64 A[4] = {0, 0, 0, 0};
    for (int lr0 = warp * CHUNK; lr0 < nrows; lr0 += STRIDE) {
        u64 E[CHUNK][4];
        float t[CHUNK];
#pragma unroll
        for (int i = 0; i < CHUNK; i++) {
            if (lr0 + i < nrows) {
                loadE(sE, lr0 + i, lane, E[i]);
                t[i] = dot8p(E[i], U);
            } else {
                E[i][0]=E[i][1]=E[i][2]=E[i][3]=0ull; t[i] = 0.f;
            }
        }
        bflyN(t, CHUNK);
#pragma unroll
        for (int i = 0; i < CHUNK; i++) {
            float r = (lr0 + i < nrows) ? svf[lr0 + i] : 0.f;
            float cbf = -(t[i] * r) * (r * INV_B);   // = -B*v^2*t
            u64 CB2 = pk2(cbf, cbf);
#pragma unroll
            for (int j = 0; j < 4; j++) A[j] = fma2(E[i][j], CB2, A[j]);
        }
    }
    blockAcc(sacc, A, lane, warp, tid, gdst);
}

// output: Q = E * (B*v3) * u3, fp32; r refined with one fp32 Newton. Packed.
__device__ __forceinline__ void outBody(const float* sE, const float* su,
                                        float* __restrict__ out, int rs,
                                        int nrows, int lane, int warp) {
    u64 U[4]; loadU(su, lane, U);
    for (int lr0 = warp * CHUNK; lr0 < nrows; lr0 += STRIDE) {
        u64 E[CHUNK][4];
        float c[CHUNK];
#pragma unroll
        for (int i = 0; i < CHUNK; i++) {
            if (lr0 + i < nrows) {
                loadE(sE, lr0 + i, lane, E[i]);
                c[i] = dot8p(E[i], U);
            } else {
                E[i][0]=E[i][1]=E[i][2]=E[i][3]=0ull; c[i] = 1.f;
            }
        }
        bflyN(c, CHUNK);
#pragma unroll
        for (int i = 0; i < CHUNK; i++) {
            int lr = lr0 + i;
            if (lr < nrows) {
                float cc = fmaxf(c[i], 1e-37f);
                float r0 = frcp(cc);
                float bs = r0 * (2.0f - cc * r0);  // refined 1/c = B*v3
                u64 BS2 = pk2(bs, bs);
                u64 o[4];
#pragma unroll
                for (int j = 0; j < 4; j++)
                    o[j] = mul2(mul2(E[i][j], BS2), U[j]);
                ulonglong2* orow = (ulonglong2*)(out + (size_t)(rs + lr) * NK);
                orow[lane]      = make_ulonglong2(o[0], o[1]);
                orow[32 + lane] = make_ulonglong2(o[2], o[3]);
            }
        }
    }
}

__global__ void __launch_bounds__(BLOCK_P, 1)
sinkhorn_persist(const float* __restrict__ fin, const float* __restrict__ win,
                 float* __restrict__ out) {
    extern __shared__ char smem[];
    double*   sred = (double*)(smem + OFF_RED);
    double*   sK2  = (double*)(smem + OFF_K2);
    double*   sR1  = (double*)(smem + OFF_R1);
    double*   sscl = (double*)(smem + OFF_SCL);
    float*    sw   = (float*) (smem + OFF_W);
    float*    sbuf = (float*) (smem + OFF_BUF);
    float*    sv1  = (float*) (smem + OFF_V1);
    float*    sv2  = (float*) (smem + OFF_V2);
    float*    su   = (float*) (smem + OFF_U);
    float*    sacc = (float*) (smem + OFF_ACC);
    float*    sE   = (float*) (smem + OFF_E);

    const int tid  = threadIdx.x;
    const int lane = tid & 31, warp = tid >> 5;
    const int bid  = blockIdx.x;
    const int rs = (NB * bid) / GRID_P;
    const int re = (NB * (bid + 1)) / GRID_P;
    const int nrows = re - rs;

    // ---- phase A: zero globals (block 0); load w; softmax(w) -> sK2 (all);
    //      stage raw f into smem E area + column-max partials ----
    if (bid == 0 && tid < NK) {
        __stcg(&g_R1[tid * GP], 0.0);
#pragma unroll
        for (int s2 = 0; s2 < 2; s2++) {
            __stcg(&g_R2[s2][tid * GP], 0.0);  __stcg(&g_R3[s2][tid * GP], 0.0);
            __stcg(&g_ub1[s2][tid * GP], 0.0); __stcg(&g_ub2[s2][tid * GP], 0.0);
            __stcg(&g_ub3[s2][tid * GP], 0.0);
        }
    }
    if (tid < NK) { float wv = win[tid]; sw[tid] = wv; sbuf[tid] = 0.f; su[tid] = wv; }
    __syncthreads();
    if (warp == 0) {
        float m = -3.4e38f;
#pragma unroll
        for (int i = 0; i < 8; i++) m = fmaxf(m, su[lane + 32*i]);
        m = warpRedMaxF(m);
        if (lane == 0) sscl[0] = (double)m;
    }
    __syncthreads();
    {   float m = (float)sscl[0];
        float ex = 0.f;
        if (tid < NK) { ex = expf(sw[tid] - m); sred[tid] = (double)ex; }
        __syncthreads();
        if (warp == 0) {
            double s = 0.0;
#pragma unroll
            for (int i = 0; i < 8; i++) s += sred[lane + 32*i];
            s = warpRedSumD(s);
            if (lane == 0) sscl[0] = s;
        }
        __syncthreads();
        float ssum = (float)sscl[0];
        if (tid < NK) sK2[tid] = (double)(ex / ssum);
    }
    {   // stage f into smem + column max (thread = (col, row-half))
        int col = tid & 255, half = tid >> 8;
        float mx = -3.4e38f;
        for (int r = rs + half; r < re; r += 2) {
            float f = fin[(size_t)r * NK + col];
            sE[(r - rs) * NK + col] = f;
            mx = fmaxf(mx, f);
        }
        atomicMax(&g_cmax[col * GPC], encf(mx));   // idempotent across replays
    }
    gridBar(tid, bid);

    // ---- phase B: E' = exp((f-colmax)*20) in place; R1 = colsum ----
    {
        int col = tid & 255, half = tid >> 8;
        float Mt = decf(__ldcg(&g_cmax[col * GPC]));
        float r1p = 0.f;
        for (int r = rs + half; r < re; r += 2) {
            float e = expf((sE[(r - rs) * NK + col] - Mt) * 20.0f);
            sE[(r - rs) * NK + col] = e;
            r1p += e;
        }
        atomicAdd(&g_R1[col * GP], (double)r1p);
    }
    gridBar(tid, bid);
    if (tid < NK) sR1[tid] = __ldcg(&g_R1[tid * GP]);
    __syncthreads();

    // ---- outer loop ----
    for (int it = 0; it < N_OUTER; ++it) {
        const int s = it & 1;
        const bool last = (it == N_OUTER - 1);

        // fwd1: u1 = K2/R1 -> sv1, R2[s]
        if (tid < NK) su[tid] = __fdividef((float)sK2[tid], (float)sR1[tid]);
        __syncthreads();
        fwdBody(sE, su, sv1, nrows, g_R2[s], sacc, lane, warp, tid);
        gridBar(tid, bid);

        // zero next iteration's accumulator slot (block 0; double-buffered:
        // slot s^1 was last read before this barrier, next written 2 bars later)
        if (bid == 0 && !last && tid < NK) {
            int t2 = s ^ 1;
            __stcg(&g_R2[t2][tid * GP], 0.0);  __stcg(&g_R3[t2][tid * GP], 0.0);
            __stcg(&g_ub1[t2][tid * GP], 0.0); __stcg(&g_ub2[t2][tid * GP], 0.0);
            __stcg(&g_ub3[t2][tid * GP], 0.0);
        }

        // fwd2: u2 = K2/R2 -> sv2, R3[s]
        if (tid < NK)
            su[tid] = __fdividef((float)sK2[tid], (float)__ldcg(&g_R2[s][tid * GP]));
        __syncthreads();
        fwdBody(sE, su, sv2, nrows, g_R3[s], sacc, lane, warp, tid);
        gridBar(tid, bid);

        if (!last) {
            // passC: u3 = K2/R3 -> ub3[s]
            if (tid < NK)
                su[tid] = __fdividef((float)sK2[tid], (float)__ldcg(&g_R3[s][tid * GP]));
            __syncthreads();
            passCBody(sE, su, fin, rs, nrows, g_ub3[s], sacc, lane, warp, tid);
            gridBar(tid, bid);

            // bwd layer 2: rb = -ub3*K2/R3^2 (K-side DP), uses sv2 -> ub2[s]
            if (tid < NK) {
                double R = __ldcg(&g_R3[s][tid * GP]);
                double rd = (double)frcp((float)R);
                su[tid] = (float)((-__ldcg(&g_ub3[s][tid * GP]) * sK2[tid] * rd) * rd);
            }
            __syncthreads();
            bwdBody(sE, su, sv2, nrows, g_ub2[s], sacc, lane, warp, tid);
            gridBar(tid, bid);

            // bwd layer 1: rb = -ub2*K2/R2^2, uses sv1 -> ub1[s]
            if (tid < NK) {
                double R = __ldcg(&g_R2[s][tid * GP]);
                double rd = (double)frcp((float)R);
                su[tid] = (float)((-__ldcg(&g_ub2[s][tid * GP]) * sK2[tid] * rd) * rd);
            }
            __syncthreads();
            bwdBody(sE, su, sv1, nrows, g_ub1[s], sacc, lane, warp, tid);
            gridBar(tid, bid);

            // ---- SGD update, redundant per block, warp-reduced ----
            double K2j = 0.0, kb = 0.0;
            if (tid < NK) {
                K2j = sK2[tid];
                kb = __ldcg(&g_ub1[s][tid * GP]) * rcpd(sR1[tid])
                   + __ldcg(&g_ub2[s][tid * GP]) * rcpd(__ldcg(&g_R2[s][tid * GP]))
                   + __ldcg(&g_ub3[s][tid * GP]) * rcpd(__ldcg(&g_R3[s][tid * GP]));
                sred[tid] = kb * K2j;
            }
            __syncthreads();
            if (warp == 0) {
                double d = 0.0;
#pragma unroll
                for (int i = 0; i < 8; i++) d += sred[lane + 32*i];
                d = warpRedSumD(d);
                if (lane == 0) sscl[0] = d;
            }
            __syncthreads();
            double dot = sscl[0];
            float gf = 0.f;
            if (tid < NK) {
                double g = K2j*(kb - dot) + 5.0*(K2j*(1.0/256.0) - (1.0/65536.0));
                gf = (float)g;
                sred[tid] = (double)gf * (double)gf;
            }
            __syncthreads();
            if (warp == 0) {
                double d = 0.0;
#pragma unroll
                for (int i = 0; i < 8; i++) d += sred[lane + 32*i];
                d = warpRedSumD(d);
                if (lane == 0) sscl[0] = sqrt(d);
            }
            __syncthreads();
            float norm = (float)sscl[0];
            if (tid < NK) {
                gf *= fminf(1.0f, 1.0f/(norm + 1e-6f));
                float bf = 0.99f*sbuf[tid] + gf; sbuf[tid] = bf;
                float wv = sw[tid] - 0.1f*bf;    sw[tid]   = wv;
                su[tid] = wv;
            }
            __syncthreads();
            if (warp == 0) {
                float m = -3.4e38f;
#pragma unroll
                for (int i = 0; i < 8; i++) m = fmaxf(m, su[lane + 32*i]);
                m = warpRedMaxF(m);
                if (lane == 0) sscl[0] = (double)m;
            }
            __syncthreads();
            float m = (float)sscl[0];
            float ex = 0.f;
            if (tid < NK) { ex = expf(sw[tid] - m); sred[tid] = (double)ex; }
            __syncthreads();
            if (warp == 0) {
                double d = 0.0;
#pragma unroll
                for (int i = 0; i < 8; i++) d += sred[lane + 32*i];
                d = warpRedSumD(d);
                if (lane == 0) sscl[0] = d;
            }
            __syncthreads();
            float ssum = (float)sscl[0];
            if (tid < NK) sK2[tid] = (double)(ex / ssum);
            __syncthreads();
        } else {
            // final: Q uses pre-update w
            if (tid < NK)
                su[tid] = __fdividef((float)sK2[tid], (float)__ldcg(&g_R3[s][tid * GP]));
            __syncthreads();
            outBody(sE, su, out, rs, nrows, lane, warp);
        }
    }
}

// ---------------------------------------------------------------------------
extern "C" void kernel_launch(void* const* d_in, const int* in_sizes, int n_in,
                              void* d_out, int out_size) {
    const float* fin = nullptr;
    const float* win = nullptr;
    for (int i = 0; i < n_in; i++) {
        if (in_sizes[i] == NB*NK)   fin = (const float*)d_in[i];
        else if (in_sizes[i] == NK) win = (const float*)d_in[i];
    }
    if (!fin) fin = (const float*)d_in[0];
    if (!win) win = (const float*)d_in[1];
    float* out = (float*)d_out;

    cudaFuncSetAttribute(sinkhorn_persist,
                         cudaFuncAttributeMaxDynamicSharedMemorySize, SMEM_TOTAL);
    sinkhorn_persist<<<GRID_P, BLOCK_P, SMEM_TOTAL>>>(fin, win, out);
}

// round 15
// speedup vs baseline: 1.1590x; 1.1590x over previous
#include <cuda_runtime.h>
#include <math.h>

// ---------------------------------------------------------------------------
// Balanced Sinkhorn, persistent single-kernel, zero per-row FP64.
// E' = exp((f - colmax)/eps) in [0,1] (column shift exactly invariant: the
// reference row-normalizes first) lives entirely in shared memory.
// Per-row scalars factored as r = 1/c so all products stay in fp32 range.
// R15: NO grid barriers in the main loop. Cross-block sync is per-column
// dataflow: each 256B accumulator line holds {double val; u32 cnt}; producers
// atomicAdd(val) then red.release(cnt); consumers acquire-poll their OWN
// line's cnt to base+148*use, then read val from the same line (2 L2 RTs vs
// ~4 for the barrier). Accumulators accumulate forever; per-launch snapshots
// (baseC/prevV, taken before the last build barrier) give exact deltas and
// make the protocol graph-replay-safe with no zeroing choreography.
// Bodies/update math identical to R13 (best: 279us).
// ---------------------------------------------------------------------------

#define NB 16384
#define NK 256
#define GRID_P 148
#define BLOCK_P 512
#define WARPS_P 16
#define N_OUTER 10
#define INV_B 6.103515625e-05f   // 1/16384 (exact)
#define CHUNK 4
#define STRIDE (WARPS_P * CHUNK)   // 64
#define CHUNK2 2
#define STRIDE2 (WARPS_P * CHUNK2) // 32
#define GP  32   // accumulator pad: 32 doubles = 256 B per logical element
#define GPC 64   // cmax pad: 64 uints = 256 B
#define NSLOT 10 // R2[0],R2[1],R3[0],R3[1],ub3[0],ub3[1],ub2[0],ub2[1],ub1[0],ub1[1]

// shared memory layout (bytes)
#define OFF_RED  0        // double[256]   2048
#define OFF_K2   2048     // double[256]   2048
#define OFF_R1   4096     // double[256]   2048
#define OFF_SCL  6144     // double[4]       64 (scalar broadcast)
#define OFF_BARS 6208     // unsigned[16]    64 (barrier scalar)
#define OFF_W    6272     // float[256]    1024
#define OFF_BUF  7296     // float[256]    1024
#define OFF_V1   8320     // float[112]     448
#define OFF_V2   8768     // float[112]     448
#define OFF_U    9216     // float[256]    1024
#define OFF_ACC  10240    // float[16*256] 16384
#define OFF_E    26624    // float[111*256] 113664
#define OFF_PREV 140288   // double[10*256] 20480 (per-launch value snapshot)
#define OFF_BASE 160768   // u32[10*256]    10240 (per-launch cnt snapshot)
#define OFF_CUR  171008   // double[5*256]  10240 (this-iteration deltas)
#define SMEM_TOTAL 181248

// Global state (allocation-free). All counters monotonic across graph replays
// (per-launch snapshots give deltas/targets); cmax idempotent.
static __device__ unsigned g_count;                              // build bars
static __device__ __align__(128) unsigned g_flag[GRID_P * 32];   // build bars
static __device__ __align__(256) unsigned g_cmax[NK * GPC];
static __device__ __align__(256) double g_R1[NK * GP];           // build-phase
// 10 dataflow slots; line layout per column: [0]=val(double), bytes 8..11=cnt
static __device__ __align__(256) double g_acc[NSLOT][NK * GP];

__device__ __forceinline__ float frcp(float x) {
    float r; asm("rcp.approx.f32 %0, %1;" : "=f"(r) : "f"(x)); return r;
}
// fp32-seeded double reciprocal with one DP Newton step (~2^-46)
__device__ __forceinline__ double rcpd(double x) {
    double r = (double)frcp((float)x);
    return r * (2.0 - x * r);
}
__device__ __forceinline__ unsigned encf(float x) {
    unsigned u = __float_as_uint(x);
    return (u & 0x80000000u) ? ~u : (u | 0x80000000u);
}
__device__ __forceinline__ float decf(unsigned e) {
    unsigned u = (e & 0x80000000u) ? (e & 0x7fffffffu) : ~e;
    return __uint_as_float(u);
}

__device__ __forceinline__ double warpRedSumD(double v) {
#pragma unroll
    for (int m = 16; m; m >>= 1) v += __shfl_xor_sync(0xffffffffu, v, m);
    return v;
}
__device__ __forceinline__ float warpRedMaxF(float v) {
#pragma unroll
    for (int m = 16; m; m >>= 1) v = fmaxf(v, __shfl_xor_sync(0xffffffffu, v, m));
    return v;
}

// interleaved butterflies (pipeline SHFL latency across independent rows)
__device__ __forceinline__ void bflyN(float* c, int n) {
#pragma unroll
    for (int m = 16; m; m >>= 1)
        for (int i = 0; i < n; i++)
            c[i] += __shfl_xor_sync(0xffffffffu, c[i], m);
}

// ---------------------------------------------------------------------------
// Build-phase grid barrier (2 uses only). R13 design: per-block flags,
// broadcast release. Monotonic epochs, replay-safe.
// ---------------------------------------------------------------------------
__device__ __forceinline__ void gridBar(unsigned* sbar, int tid, int bid) {
    __syncthreads();
    if (tid == 0) {
        unsigned t;
        asm volatile("atom.acq_rel.gpu.global.add.u32 %0, [%1], 1;"
                     : "=r"(t) : "l"(&g_count) : "memory");
        *sbar = t;
    }
    __syncthreads();
    unsigned t = *sbar;
    unsigned epoch = t / GRID_P + 1u;
    if ((t % GRID_P) == GRID_P - 1u) {
        if (tid < GRID_P)
            asm volatile("st.release.gpu.global.u32 [%0], %1;"
                         :: "l"(&g_flag[tid * 32]), "r"(epoch) : "memory");
    }
    if (tid == 0) {
        unsigned v;
        do {
            asm volatile("ld.acquire.gpu.global.u32 %0, [%1];"
                         : "=r"(v) : "l"(&g_flag[bid * 32]) : "memory");
        } while (v < epoch);
    }
    __syncthreads();
}

// ---------------------------------------------------------------------------
// Dataflow post/consume on the 10 slots.
// ---------------------------------------------------------------------------
// producer side (inside blockAcc): val atomicAdd then cnt red.release (same line)
__device__ __forceinline__ void blockAcc(float* sacc, const float a[8],
                                         int lane, int warp, int tid,
                                         double* gdst) {
    float4* dst = (float4*)(sacc + warp * NK);
    dst[lane]      = make_float4(a[0], a[1], a[2], a[3]);
    dst[32 + lane] = make_float4(a[4], a[5], a[6], a[7]);
    __syncthreads();
    if (tid < NK) {
        float s = 0.f;
#pragma unroll
        for (int w = 0; w < WARPS_P; w++) s += sacc[w * NK + tid];
        double* vp = &gdst[tid * GP];
        atomicAdd(vp, (double)s);
        unsigned* cp = (unsigned*)vp + 2;   // byte offset 8, same 256B line
        asm volatile("red.release.gpu.global.add.u32 [%0], 1;"
                     :: "l"(cp) : "memory");
    }
}

// consumer side: poll own line's cnt to base+148*use, read val, return delta
__device__ __forceinline__ double consume(int k, int col, unsigned use,
                                          unsigned* sBaseC, double* sPrevV) {
    double* vp = &g_acc[k][col * GP];
    unsigned* cp = (unsigned*)vp + 2;
    unsigned tgt = sBaseC[k * NK + col] + 148u * use;
    unsigned v;
    do {
        asm volatile("ld.acquire.gpu.global.u32 %0, [%1];"
                     : "=r"(v) : "l"(cp) : "memory");
    } while ((int)(v - tgt) < 0);           // wrap-safe
    double now = __ldcg(vp);
    double d = now - sPrevV[k * NK + col];
    sPrevV[k * NK + col] = now;
    return d;
}

// ---------------------------------------------------------------------------
// Pass bodies: byte-identical math to R13 (best passing kernel).
// ---------------------------------------------------------------------------
// fwd: c[b]=sum u*E; r=1/c stored; Rout[k] += E*(r/B). E retained in regs.
__device__ __forceinline__ void fwdBody(const float* sE, const float* su,
                                        float* svf, int nrows, double* Rout,
                                        float* sacc, int lane, int warp, int tid) {
    float4 u0 = ((const float4*)su)[lane];
    float4 u1 = ((const float4*)su)[32 + lane];
    float a[8];
#pragma unroll
    for (int i = 0; i < 8; i++) a[i] = 0.f;
    for (int lr0 = warp * CHUNK; lr0 < nrows; lr0 += STRIDE) {
        float4 E0[CHUNK], E1[CHUNK];
        float c[CHUNK];
#pragma unroll
        for (int i = 0; i < CHUNK; i++) {
            if (lr0 + i < nrows) {
                const float4* row = (const float4*)(sE + (lr0 + i) * NK);
                E0[i] = row[lane]; E1[i] = row[32 + lane];
                c[i] = E0[i].x*u0.x + E0[i].y*u0.y + E0[i].z*u0.z + E0[i].w*u0.w
                     + E1[i].x*u1.x + E1[i].y*u1.y + E1[i].z*u1.z + E1[i].w*u1.w;
            } else {
                E0[i] = make_float4(0,0,0,0); E1[i] = E0[i]; c[i] = 1.f;
            }
        }
        bflyN(c, CHUNK);
#pragma unroll
        for (int i = 0; i < CHUNK; i++) {
            float r = frcp(fmaxf(c[i], 1e-37f));
            if (lane == 0 && lr0 + i < nrows) svf[lr0 + i] = r;
            float vf = r * INV_B;
            a[0] += E0[i].x*vf; a[1] += E0[i].y*vf; a[2] += E0[i].z*vf; a[3] += E0[i].w*vf;
            a[4] += E1[i].x*vf; a[5] += E1[i].y*vf; a[6] += E1[i].z*vf; a[7] += E1[i].w*vf;
        }
    }
    blockAcc(sacc, a, lane, warp, tid, Rout);
}

// passC (3rd fwd fused with bwd layer 3), CHUNK2 with E,P retained:
//  c, s = sum u*E{,*P}; r=1/c; v3=r/B; cbar=(s*r)*v3; ub3 += E*(cbar - v3*P)
__device__ __forceinline__ void passCBody(const float* sE, const float* su,
                                          const float* __restrict__ fin, int rs,
                                          int nrows, double* gdst, float* sacc,
                                          int lane, int warp, int tid) {
    float4 u0 = ((const float4*)su)[lane];
    float4 u1 = ((const float4*)su)[32 + lane];
    float a[8];
#pragma unroll
    for (int i = 0; i < 8; i++) a[i] = 0.f;
    for (int lr0 = warp * CHUNK2; lr0 < nrows; lr0 += STRIDE2) {
        float4 E0[CHUNK2], E1[CHUNK2], P0[CHUNK2], P1[CHUNK2];
        float c[CHUNK2], s[CHUNK2];
#pragma unroll
        for (int i = 0; i < CHUNK2; i++) {
            if (lr0 + i < nrows) {
                const float4* row  = (const float4*)(sE + (lr0 + i) * NK);
                const float4* frow = (const float4*)(fin + (size_t)(rs + lr0 + i) * NK);
                E0[i] = row[lane]; E1[i] = row[32 + lane];
                P0[i] = frow[lane]; P1[i] = frow[32 + lane];
                float t00 = E0[i].x*u0.x, t01 = E0[i].y*u0.y,
                      t02 = E0[i].z*u0.z, t03 = E0[i].w*u0.w;
                float t10 = E1[i].x*u1.x, t11 = E1[i].y*u1.y,
                      t12 = E1[i].z*u1.z, t13 = E1[i].w*u1.w;
                c[i] = t00+t01+t02+t03 + t10+t11+t12+t13;
                s[i] = t00*P0[i].x + t01*P0[i].y + t02*P0[i].z + t03*P0[i].w
                     + t10*P1[i].x + t11*P1[i].y + t12*P1[i].z + t13*P1[i].w;
            } else {
                E0[i] = make_float4(0,0,0,0); E1[i] = E0[i];
                P0[i] = E0[i]; P1[i] = E0[i];
                c[i] = 1.f; s[i] = 0.f;
            }
        }
        bflyN(c, CHUNK2);
        bflyN(s, CHUNK2);
#pragma unroll
        for (int i = 0; i < CHUNK2; i++) {
            float r = frcp(fmaxf(c[i], 1e-37f));
            float v3f = r * INV_B;
            float cbf = (s[i] * r) * v3f;     // = B*v3^2*s, overflow-safe order
            a[0] += E0[i].x*(cbf - v3f*P0[i].x); a[1] += E0[i].y*(cbf - v3f*P0[i].y);
            a[2] += E0[i].z*(cbf - v3f*P0[i].z); a[3] += E0[i].w*(cbf - v3f*P0[i].w);
            a[4] += E1[i].x*(cbf - v3f*P1[i].x); a[5] += E1[i].y*(cbf - v3f*P1[i].y);
            a[6] += E1[i].z*(cbf - v3f*P1[i].z); a[7] += E1[i].w*(cbf - v3f*P1[i].w);
        }
    }
    blockAcc(sacc, a, lane, warp, tid, gdst);
}

// bwd layer: t[b]=sum rb*E; cb=-(t*r)*(r/B); ub_out += E*cb. E retained.
__device__ __forceinline__ void bwdBody(const float* sE, const float* su,
                                        const float* svf, int nrows, double* gdst,
                                        float* sacc, int lane, int warp, int tid) {
    float4 b0 = ((const float4*)su)[lane];
    float4 b1 = ((const float4*)su)[32 + lane];
    float a[8];
#pragma unroll
    for (int i = 0; i < 8; i++) a[i] = 0.f;
    for (int lr0 = warp * CHUNK; lr0 < nrows; lr0 += STRIDE) {
        float4 E0[CHUNK], E1[CHUNK];
        float t[CHUNK];
#pragma unroll
        for (int i = 0; i < CHUNK; i++) {
            if (lr0 + i < nrows) {
                const float4* row = (const float4*)(sE + (lr0 + i) * NK);
                E0[i] = row[lane]; E1[i] = row[32 + lane];
                t[i] = E0[i].x*b0.x + E0[i].y*b0.y + E0[i].z*b0.z + E0[i].w*b0.w
                     + E1[i].x*b1.x + E1[i].y*b1.y + E1[i].z*b1.z + E1[i].w*b1.w;
            } else {
                E0[i] = make_float4(0,0,0,0); E1[i] = E0[i]; t[i] = 0.f;
            }
        }
        bflyN(t, CHUNK);
#pragma unroll
        for (int i = 0; i < CHUNK; i++) {
            float r = (lr0 + i < nrows) ? svf[lr0 + i] : 0.f;
            float cbf = -(t[i] * r) * (r * INV_B);   // = -B*v^2*t
            a[0] += E0[i].x*cbf; a[1] += E0[i].y*cbf; a[2] += E0[i].z*cbf; a[3] += E0[i].w*cbf;
            a[4] += E1[i].x*cbf; a[5] += E1[i].y*cbf; a[6] += E1[i].z*cbf; a[7] += E1[i].w*cbf;
        }
    }
    blockAcc(sacc, a, lane, warp, tid, gdst);
}

// output: Q = E * (B*v3) * u3, fp32; r refined with one fp32 Newton. Retained E.
__device__ __forceinline__ void outBody(const float* sE, const float* su,
                                        float* __restrict__ out, int rs,
                                        int nrows, int lane, int warp) {
    float4 u0 = ((const float4*)su)[lane];
    float4 u1 = ((const float4*)su)[32 + lane];
    for (int lr0 = warp * CHUNK; lr0 < nrows; lr0 += STRIDE) {
        float4 E0[CHUNK], E1[CHUNK];
        float c[CHUNK];
#pragma unroll
        for (int i = 0; i < CHUNK; i++) {
            if (lr0 + i < nrows) {
                const float4* row = (const float4*)(sE + (lr0 + i) * NK);
                E0[i] = row[lane]; E1[i] = row[32 + lane];
                c[i] = E0[i].x*u0.x + E0[i].y*u0.y + E0[i].z*u0.z + E0[i].w*u0.w
                     + E1[i].x*u1.x + E1[i].y*u1.y + E1[i].z*u1.z + E1[i].w*u1.w;
            } else {
                E0[i] = make_float4(0,0,0,0); E1[i] = E0[i]; c[i] = 1.f;
            }
        }
        bflyN(c, CHUNK);
#pragma unroll
        for (int i = 0; i < CHUNK; i++) {
            int lr = lr0 + i;
            if (lr < nrows) {
                float cc = fmaxf(c[i], 1e-37f);
                float r0 = frcp(cc);
                float bs = r0 * (2.0f - cc * r0);  // refined 1/c = B*v3
                float4 o0, o1;
                o0.x = (E0[i].x*bs)*u0.x; o0.y = (E0[i].y*bs)*u0.y;
                o0.z = (E0[i].z*bs)*u0.z; o0.w = (E0[i].w*bs)*u0.w;
                o1.x = (E1[i].x*bs)*u1.x; o1.y = (E1[i].y*bs)*u1.y;
                o1.z = (E1[i].z*bs)*u1.z; o1.w = (E1[i].w*bs)*u1.w;
                float4* orow = (float4*)(out + (size_t)(rs + lr) * NK);
                orow[lane] = o0;
                orow[32 + lane] = o1;
            }
        }
    }
}

__global__ void __launch_bounds__(BLOCK_P, 1)
sinkhorn_persist(const float* __restrict__ fin, const float* __restrict__ win,
                 float* __restrict__ out) {
    extern __shared__ char smem[];
    double*   sred  = (double*)(smem + OFF_RED);
    double*   sK2   = (double*)(smem + OFF_K2);
    double*   sR1   = (double*)(smem + OFF_R1);
    double*   sscl  = (double*)(smem + OFF_SCL);
    unsigned* sbar  = (unsigned*)(smem + OFF_BARS);
    float*    sw    = (float*) (smem + OFF_W);
    float*    sbuf  = (float*) (smem + OFF_BUF);
    float*    sv1   = (float*) (smem + OFF_V1);
    float*    sv2   = (float*) (smem + OFF_V2);
    float*    su    = (float*) (smem + OFF_U);
    float*    sacc  = (float*) (smem + OFF_ACC);
    float*    sE    = (float*) (smem + OFF_E);
    double*   sPrevV= (double*)(smem + OFF_PREV);
    unsigned* sBaseC= (unsigned*)(smem + OFF_BASE);
    double*   sCur  = (double*)(smem + OFF_CUR);  // [0]=R2,[1]=R3,[2]=ub3,[3]=ub2,[4]=ub1

    const int tid  = threadIdx.x;
    const int lane = tid & 31, warp = tid >> 5;
    const int bid  = blockIdx.x;
    const int rs = (NB * bid) / GRID_P;
    const int re = (NB * (bid + 1)) / GRID_P;
    const int nrows = re - rs;

    // ---- phase A: zero R1 (block 0); load w; softmax(w) -> sK2 (all);
    //      stage raw f into smem E area + column-max partials ----
    if (bid == 0 && tid < NK) __stcg(&g_R1[tid * GP], 0.0);
    if (tid < NK) { float wv = win[tid]; sw[tid] = wv; sbuf[tid] = 0.f; su[tid] = wv; }
    __syncthreads();
    if (warp == 0) {
        float m = -3.4e38f;
#pragma unroll
        for (int i = 0; i < 8; i++) m = fmaxf(m, su[lane + 32*i]);
        m = warpRedMaxF(m);
        if (lane == 0) sscl[0] = (double)m;
    }
    __syncthreads();
    {   float m = (float)sscl[0];
        float ex = 0.f;
        if (tid < NK) { ex = expf(sw[tid] - m); sred[tid] = (double)ex; }
        __syncthreads();
        if (warp == 0) {
            double s = 0.0;
#pragma unroll
            for (int i = 0; i < 8; i++) s += sred[lane + 32*i];
            s = warpRedSumD(s);
            if (lane == 0) sscl[0] = s;
        }
        __syncthreads();
        float ssum = (float)sscl[0];
        if (tid < NK) sK2[tid] = (double)(ex / ssum);
    }
    {   // stage f into smem + column max (thread = (col, row-half))
        int col = tid & 255, half = tid >> 8;
        float mx = -3.4e38f;
        for (int r = rs + half; r < re; r += 2) {
            float f = fin[(size_t)r * NK + col];
            sE[(r - rs) * NK + col] = f;
            mx = fmaxf(mx, f);
        }
        atomicMax(&g_cmax[col * GPC], encf(mx));   // idempotent across replays
    }
    gridBar(sbar, tid, bid);

    // ---- phase B: E' = exp((f-colmax)*20) in place; R1 = colsum;
    //      snapshot the 10 dataflow slots (stable: no loop posts yet) ----
    {
        int col = tid & 255, half = tid >> 8;
        float Mt = decf(__ldcg(&g_cmax[col * GPC]));
        float r1p = 0.f;
        for (int r = rs + half; r < re; r += 2) {
            float e = expf((sE[(r - rs) * NK + col] - Mt) * 20.0f);
            sE[(r - rs) * NK + col] = e;
            r1p += e;
        }
        atomicAdd(&g_R1[col * GP], (double)r1p);
    }
    if (tid < NK) {
#pragma unroll
        for (int k = 0; k < NSLOT; k++) {
            double* vp = &g_acc[k][tid * GP];
            sPrevV[k * NK + tid] = __ldcg(vp);
            sBaseC[k * NK + tid] = __ldcg((const unsigned*)vp + 2);
        }
    }
    gridBar(sbar, tid, bid);
    if (tid < NK) sR1[tid] = __ldcg(&g_R1[tid * GP]);
    __syncthreads();

    // ---- outer loop: NO grid barriers, pure per-column dataflow ----
    for (int it = 0; it < N_OUTER; ++it) {
        const int s = it & 1;
        const bool last = (it == N_OUTER - 1);
        const unsigned use = (unsigned)(it >> 1) + 1u;

        // fwd1: u1 = K2/R1 (block-local) -> sv1, post R2[s] (slot 0+s)
        if (tid < NK) su[tid] = __fdividef((float)sK2[tid], (float)sR1[tid]);
        __syncthreads();
        fwdBody(sE, su, sv1, nrows, g_acc[0 + s], sacc, lane, warp, tid);

        // fwd2: consume R2[s] -> sv2, post R3[s] (slot 2+s)
        if (tid < NK) {
            double d = consume(0 + s, tid, use, sBaseC, sPrevV);
            sCur[0 * NK + tid] = d;
            su[tid] = __fdividef((float)sK2[tid], (float)d);
        }
        __syncthreads();
        fwdBody(sE, su, sv2, nrows, g_acc[2 + s], sacc, lane, warp, tid);

        if (!last) {
            // passC: consume R3[s], post ub3[s] (slot 4+s)
            if (tid < NK) {
                double d = consume(2 + s, tid, use, sBaseC, sPrevV);
                sCur[1 * NK + tid] = d;
                su[tid] = __fdividef((float)sK2[tid], (float)d);
            }
            __syncthreads();
            passCBody(sE, su, fin, rs, nrows, g_acc[4 + s], sacc, lane, warp, tid);

            // bwd2: consume ub3[s]; rb = -ub3*K2/R3^2; post ub2[s] (slot 6+s)
            if (tid < NK) {
                double u3 = consume(4 + s, tid, use, sBaseC, sPrevV);
                sCur[2 * NK + tid] = u3;
                double R = sCur[1 * NK + tid];
                double rd = (double)frcp((float)R);
                su[tid] = (float)((-u3 * sK2[tid] * rd) * rd);
            }
            __syncthreads();
            bwdBody(sE, su, sv2, nrows, g_acc[6 + s], sacc, lane, warp, tid);

            // bwd1: consume ub2[s]; rb = -ub2*K2/R2^2; post ub1[s] (slot 8+s)
            if (tid < NK) {
                double u2 = consume(6 + s, tid, use, sBaseC, sPrevV);
                sCur[3 * NK + tid] = u2;
                double R = sCur[0 * NK + tid];
                double rd = (double)frcp((float)R);
                su[tid] = (float)((-u2 * sK2[tid] * rd) * rd);
            }
            __syncthreads();
            bwdBody(sE, su, sv1, nrows, g_acc[8 + s], sacc, lane, warp, tid);

            // ---- SGD update (redundant per block, deterministic: all blocks
            //      see identical settled vals and snapshots) ----
            double K2j = 0.0, kb = 0.0;
            if (tid < NK) {
                double u1 = consume(8 + s, tid, use, sBaseC, sPrevV);
                sCur[4 * NK + tid] = u1;
                K2j = sK2[tid];
                kb = u1 * rcpd(sR1[tid])
                   + sCur[3 * NK + tid] * rcpd(sCur[0 * NK + tid])
                   + sCur[2 * NK + tid] * rcpd(sCur[1 * NK + tid]);
                sred[tid] = kb * K2j;
            }
            __syncthreads();
            if (warp == 0) {
                double d = 0.0;
#pragma unroll
                for (int i = 0; i < 8; i++) d += sred[lane + 32*i];
                d = warpRedSumD(d);
                if (lane == 0) sscl[0] = d;
            }
            __syncthreads();
            double dot = sscl[0];
            float gf = 0.f;
            if (tid < NK) {
                double g = K2j*(kb - dot) + 5.0*(K2j*(1.0/256.0) - (1.0/65536.0));
                gf = (float)g;
                sred[tid] = (double)gf * (double)gf;
            }
            __syncthreads();
            if (warp == 0) {
                double d = 0.0;
#pragma unroll
                for (int i = 0; i < 8; i++) d += sred[lane + 32*i];
                d = warpRedSumD(d);
                if (lane == 0) sscl[0] = sqrt(d);
            }
            __syncthreads();
            float norm = (float)sscl[0];
            if (tid < NK) {
                gf *= fminf(1.0f, 1.0f/(norm + 1e-6f));
                float bf = 0.99f*sbuf[tid] + gf; sbuf[tid] = bf;
                float wv = sw[tid] - 0.1f*bf;    sw[tid]   = wv;
                su[tid] = wv;
            }
            __syncthreads();
            if (warp == 0) {
                float m = -3.4e38f;
#pragma unroll
                for (int i = 0; i < 8; i++) m = fmaxf(m, su[lane + 32*i]);
                m = warpRedMaxF(m);
                if (lane == 0) sscl[0] = (double)m;
            }
            __syncthreads();
            float m = (float)sscl[0];
            float ex = 0.f;
            if (tid < NK) { ex = expf(sw[tid] - m); sred[tid] = (double)ex; }
            __syncthreads();
            if (warp == 0) {
                double d = 0.0;
#pragma unroll
                for (int i = 0; i < 8; i++) d += sred[lane + 32*i];
                d = warpRedSumD(d);
                if (lane == 0) sscl[0] = d;
            }
            __syncthreads();
            float ssum = (float)sscl[0];
            if (tid < NK) sK2[tid] = (double)(ex / ssum);
            __syncthreads();
        } else {
            // final: consume R3[s]; Q uses pre-update w
            if (tid < NK) {
                double d = consume(2 + s, tid, use, sBaseC, sPrevV);
                su[tid] = __fdividef((float)sK2[tid], (float)d);
            }
            __syncthreads();
            outBody(sE, su, out, rs, nrows, lane, warp);
        }
    }
}

// ---------------------------------------------------------------------------
extern "C" void kernel_launch(void* const* d_in, const int* in_sizes, int n_in,
                              void* d_out, int out_size) {
    const float* fin = nullptr;
    const float* win = nullptr;
    for (int i = 0; i < n_in; i++) {
        if (in_sizes[i] == NB*NK)   fin = (const float*)d_in[i];
        else if (in_sizes[i] == NK) win = (const float*)d_in[i];
    }
    if (!fin) fin = (const float*)d_in[0];
    if (!win) win = (const float*)d_in[1];
    float* out = (float*)d_out;

    cudaFuncSetAttribute(sinkhorn_persist,
                         cudaFuncAttributeMaxDynamicSharedMemorySize, SMEM_TOTAL);
    sinkhorn_persist<<<GRID_P, BLOCK_P, SMEM_TOTAL>>>(fin, win, out);
}

// round 16
// speedup vs baseline: 1.1941x; 1.0303x over previous
#include <cuda_runtime.h>
#include <math.h>

// ---------------------------------------------------------------------------
// Balanced Sinkhorn, persistent single-kernel, zero per-row FP64.
// E' = exp((f - colmax)/eps) in [0,1] (column shift exactly invariant: the
// reference row-normalizes first) lives entirely in shared memory.
// Per-row scalars factored as r = 1/c so all products stay in fp32 range.
// R16: 1024 threads/block (32 warps, occ 25%->50%) — the one untested axis
// after three sync-protocol redesigns proved neutral. Bodies and straggler
// spread are latency-limited at 16 warps; 32 warps halve both. CHUNK 4->2
// (passC ->1) to fit the forced <=64-reg budget. Everything else (barrier,
// double-buffered accumulators, update math) is byte-identical to R13 (279us).
// ---------------------------------------------------------------------------

#define NB 16384
#define NK 256
#define GRID_P 148
#define BLOCK_P 1024
#define WARPS_P 32
#define N_OUTER 10
#define INV_B 6.103515625e-05f   // 1/16384 (exact)
#define CHUNK 2
#define STRIDE (WARPS_P * CHUNK)   // 64
#define CHUNK2 1
#define STRIDE2 (WARPS_P * CHUNK2) // 32
#define GP  32   // accumulator pad: 32 doubles = 256 B per logical element
#define GPC 64   // cmax pad: 64 uints = 256 B

// shared memory layout (bytes)
#define OFF_RED  0        // double[256]   2048
#define OFF_K2   2048     // double[256]   2048
#define OFF_R1   4096     // double[256]   2048
#define OFF_SCL  6144     // double[4]       64 (scalar broadcast)
#define OFF_BARS 6208     // unsigned[16]    64 (barrier scalar)
#define OFF_W    6272     // float[256]    1024
#define OFF_BUF  7296     // float[256]    1024
#define OFF_V1   8320     // float[112]     448
#define OFF_V2   8768     // float[112]     448
#define OFF_U    9216     // float[256]    1024
#define OFF_ACC  10240    // float[32*256] 32768
#define OFF_E    43008    // float[111*256] 113664
#define SMEM_TOTAL 156672

// Global state (allocation-free). Barrier counter/flags monotonic across graph
// replays (uniform fixed barrier count per launch); accumulators re-zeroed
// inside the kernel each launch; cmax idempotent. All accumulators 256B-strided.
static __device__ unsigned g_count;                              // arrivals
static __device__ __align__(128) unsigned g_flag[GRID_P * 32];   // 128B-padded
static __device__ __align__(256) unsigned g_cmax[NK * GPC];
static __device__ __align__(256) double g_R1[NK * GP];
static __device__ __align__(256) double g_R2[2][NK * GP], g_R3[2][NK * GP];
static __device__ __align__(256) double g_ub1[2][NK * GP], g_ub2[2][NK * GP],
                                        g_ub3[2][NK * GP];

__device__ __forceinline__ float frcp(float x) {
    float r; asm("rcp.approx.f32 %0, %1;" : "=f"(r) : "f"(x)); return r;
}
// fp32-seeded double reciprocal with one DP Newton step (~2^-46)
__device__ __forceinline__ double rcpd(double x) {
    double r = (double)frcp((float)x);
    return r * (2.0 - x * r);
}
__device__ __forceinline__ unsigned encf(float x) {
    unsigned u = __float_as_uint(x);
    return (u & 0x80000000u) ? ~u : (u | 0x80000000u);
}
__device__ __forceinline__ float decf(unsigned e) {
    unsigned u = (e & 0x80000000u) ? (e & 0x7fffffffu) : ~e;
    return __uint_as_float(u);
}

__device__ __forceinline__ double warpRedSumD(double v) {
#pragma unroll
    for (int m = 16; m; m >>= 1) v += __shfl_xor_sync(0xffffffffu, v, m);
    return v;
}
__device__ __forceinline__ float warpRedMaxF(float v) {
#pragma unroll
    for (int m = 16; m; m >>= 1) v = fmaxf(v, __shfl_xor_sync(0xffffffffu, v, m));
    return v;
}

// interleaved butterflies (pipeline SHFL latency across independent rows)
__device__ __forceinline__ void bflyN(float* c, int n) {
#pragma unroll
    for (int m = 16; m; m >>= 1)
        for (int i = 0; i < n; i++)
            c[i] += __shfl_xor_sync(0xffffffffu, c[i], m);
}

// ---------------------------------------------------------------------------
// Grid barrier (R13 design, proven): per-block flags, broadcast release.
// Monotonic epochs: old/GRID+1, poll >=. Safe across graph replays.
// ---------------------------------------------------------------------------
__device__ __forceinline__ void gridBar(unsigned* sbar, int tid, int bid) {
    __syncthreads();
    if (tid == 0) {
        unsigned t;
        asm volatile("atom.acq_rel.gpu.global.add.u32 %0, [%1], 1;"
                     : "=r"(t) : "l"(&g_count) : "memory");
        *sbar = t;
    }
    __syncthreads();
    unsigned t = *sbar;
    unsigned epoch = t / GRID_P + 1u;
    if ((t % GRID_P) == GRID_P - 1u) {          // this block is the releaser
        if (tid < GRID_P)
            asm volatile("st.release.gpu.global.u32 [%0], %1;"
                         :: "l"(&g_flag[tid * 32]), "r"(epoch) : "memory");
    }
    if (tid == 0) {
        unsigned v;
        do {
            asm volatile("ld.acquire.gpu.global.u32 %0, [%1];"
                         : "=r"(v) : "l"(&g_flag[bid * 32]) : "memory");
        } while (v < epoch);
    }
    __syncthreads();
}

// per-warp fp32 partials -> block fp32 -> global fp64 atomic (256B-strided dst)
__device__ __forceinline__ void blockAcc(float* sacc, const float a[8],
                                         int lane, int warp, int tid,
                                         double* gdst) {
    float4* dst = (float4*)(sacc + warp * NK);
    dst[lane]      = make_float4(a[0], a[1], a[2], a[3]);
    dst[32 + lane] = make_float4(a[4], a[5], a[6], a[7]);
    __syncthreads();
    if (tid < NK) {
        float s = 0.f;
#pragma unroll
        for (int w = 0; w < WARPS_P; w++) s += sacc[w * NK + tid];
        atomicAdd(&gdst[tid * GP], (double)s);
    }
}

// fwd: c[b]=sum u*E; r=1/c stored; Rout[k] += E*(r/B). E retained in regs.
__device__ __forceinline__ void fwdBody(const float* sE, const float* su,
                                        float* svf, int nrows, double* Rout,
                                        float* sacc, int lane, int warp, int tid) {
    float4 u0 = ((const float4*)su)[lane];
    float4 u1 = ((const float4*)su)[32 + lane];
    float a[8];
#pragma unroll
    for (int i = 0; i < 8; i++) a[i] = 0.f;
    for (int lr0 = warp * CHUNK; lr0 < nrows; lr0 += STRIDE) {
        float4 E0[CHUNK], E1[CHUNK];
        float c[CHUNK];
#pragma unroll
        for (int i = 0; i < CHUNK; i++) {
            if (lr0 + i < nrows) {
                const float4* row = (const float4*)(sE + (lr0 + i) * NK);
                E0[i] = row[lane]; E1[i] = row[32 + lane];
                c[i] = E0[i].x*u0.x + E0[i].y*u0.y + E0[i].z*u0.z + E0[i].w*u0.w
                     + E1[i].x*u1.x + E1[i].y*u1.y + E1[i].z*u1.z + E1[i].w*u1.w;
            } else {
                E0[i] = make_float4(0,0,0,0); E1[i] = E0[i]; c[i] = 1.f;
            }
        }
        bflyN(c, CHUNK);
#pragma unroll
        for (int i = 0; i < CHUNK; i++) {
            float r = frcp(fmaxf(c[i], 1e-37f));
            if (lane == 0 && lr0 + i < nrows) svf[lr0 + i] = r;
            float vf = r * INV_B;
            a[0] += E0[i].x*vf; a[1] += E0[i].y*vf; a[2] += E0[i].z*vf; a[3] += E0[i].w*vf;
            a[4] += E1[i].x*vf; a[5] += E1[i].y*vf; a[6] += E1[i].z*vf; a[7] += E1[i].w*vf;
        }
    }
    blockAcc(sacc, a, lane, warp, tid, Rout);
}

// passC (3rd fwd fused with bwd layer 3), CHUNK2=1 with E,P retained:
//  c, s = sum u*E{,*P}; r=1/c; v3=r/B; cbar=(s*r)*v3; ub3 += E*(cbar - v3*P)
__device__ __forceinline__ void passCBody(const float* sE, const float* su,
                                          const float* __restrict__ fin, int rs,
                                          int nrows, double* gdst, float* sacc,
                                          int lane, int warp, int tid) {
    float4 u0 = ((const float4*)su)[lane];
    float4 u1 = ((const float4*)su)[32 + lane];
    float a[8];
#pragma unroll
    for (int i = 0; i < 8; i++) a[i] = 0.f;
    for (int lr = warp * CHUNK2; lr < nrows; lr += STRIDE2) {
        const float4* row  = (const float4*)(sE + lr * NK);
        const float4* frow = (const float4*)(fin + (size_t)(rs + lr) * NK);
        float4 E0 = row[lane], E1 = row[32 + lane];
        float4 P0 = frow[lane], P1 = frow[32 + lane];
        float t00 = E0.x*u0.x, t01 = E0.y*u0.y, t02 = E0.z*u0.z, t03 = E0.w*u0.w;
        float t10 = E1.x*u1.x, t11 = E1.y*u1.y, t12 = E1.z*u1.z, t13 = E1.w*u1.w;
        float c = t00+t01+t02+t03 + t10+t11+t12+t13;
        float s = t00*P0.x + t01*P0.y + t02*P0.z + t03*P0.w
                + t10*P1.x + t11*P1.y + t12*P1.z + t13*P1.w;
        bflyN(&c, 1);
        bflyN(&s, 1);
        float r = frcp(fmaxf(c, 1e-37f));
        float v3f = r * INV_B;
        float cbf = (s * r) * v3f;            // = B*v3^2*s, overflow-safe order
        a[0] += E0.x*(cbf - v3f*P0.x); a[1] += E0.y*(cbf - v3f*P0.y);
        a[2] += E0.z*(cbf - v3f*P0.z); a[3] += E0.w*(cbf - v3f*P0.w);
        a[4] += E1.x*(cbf - v3f*P1.x); a[5] += E1.y*(cbf - v3f*P1.y);
        a[6] += E1.z*(cbf - v3f*P1.z); a[7] += E1.w*(cbf - v3f*P1.w);
    }
    blockAcc(sacc, a, lane, warp, tid, gdst);
}

// bwd layer: t[b]=sum rb*E; cb=-(t*r)*(r/B); ub_out += E*cb. E retained.
__device__ __forceinline__ void bwdBody(const float* sE, const float* su,
                                        const float* svf, int nrows, double* gdst,
                                        float* sacc, int lane, int warp, int tid) {
    float4 b0 = ((const float4*)su)[lane];
    float4 b1 = ((const float4*)su)[32 + lane];
    float a[8];
#pragma unroll
    for (int i = 0; i < 8; i++) a[i] = 0.f;
    for (int lr0 = warp * CHUNK; lr0 < nrows; lr0 += STRIDE) {
        float4 E0[CHUNK], E1[CHUNK];
        float t[CHUNK];
#pragma unroll
        for (int i = 0; i < CHUNK; i++) {
            if (lr0 + i < nrows) {
                const float4* row = (const float4*)(sE + (lr0 + i) * NK);
                E0[i] = row[lane]; E1[i] = row[32 + lane];
                t[i] = E0[i].x*b0.x + E0[i].y*b0.y + E0[i].z*b0.z + E0[i].w*b0.w
                     + E1[i].x*b1.x + E1[i].y*b1.y + E1[i].z*b1.z + E1[i].w*b1.w;
            } else {
                E0[i] = make_float4(0,0,0,0); E1[i] = E0[i]; t[i] = 0.f;
            }
        }
        bflyN(t, CHUNK);
#pragma unroll
        for (int i = 0; i < CHUNK; i++) {
            float r = (lr0 + i < nrows) ? svf[lr0 + i] : 0.f;
            float cbf = -(t[i] * r) * (r * INV_B);   // = -B*v^2*t
            a[0] += E0[i].x*cbf; a[1] += E0[i].y*cbf; a[2] += E0[i].z*cbf; a[3] += E0[i].w*cbf;
            a[4] += E1[i].x*cbf; a[5] += E1[i].y*cbf; a[6] += E1[i].z*cbf; a[7] += E1[i].w*cbf;
        }
    }
    blockAcc(sacc, a, lane, warp, tid, gdst);
}

// output: Q = E * (B*v3) * u3, fp32; r refined with one fp32 Newton. Retained E.
__device__ __forceinline__ void outBody(const float* sE, const float* su,
                                        float* __restrict__ out, int rs,
                                        int nrows, int lane, int warp) {
    float4 u0 = ((const float4*)su)[lane];
    float4 u1 = ((const float4*)su)[32 + lane];
    for (int lr0 = warp * CHUNK; lr0 < nrows; lr0 += STRIDE) {
        float4 E0[CHUNK], E1[CHUNK];
        float c[CHUNK];
#pragma unroll
        for (int i = 0; i < CHUNK; i++) {
            if (lr0 + i < nrows) {
                const float4* row = (const float4*)(sE + (lr0 + i) * NK);
                E0[i] = row[lane]; E1[i] = row[32 + lane];
                c[i] = E0[i].x*u0.x + E0[i].y*u0.y + E0[i].z*u0.z + E0[i].w*u0.w
                     + E1[i].x*u1.x + E1[i].y*u1.y + E1[i].z*u1.z + E1[i].w*u1.w;
            } else {
                E0[i] = make_float4(0,0,0,0); E1[i] = E0[i]; c[i] = 1.f;
            }
        }
        bflyN(c, CHUNK);
#pragma unroll
        for (int i = 0; i < CHUNK; i++) {
            int lr = lr0 + i;
            if (lr < nrows) {
                float cc = fmaxf(c[i], 1e-37f);
                float r0 = frcp(cc);
                float bs = r0 * (2.0f - cc * r0);  // refined 1/c = B*v3
                float4 o0, o1;
                o0.x = (E0[i].x*bs)*u0.x; o0.y = (E0[i].y*bs)*u0.y;
                o0.z = (E0[i].z*bs)*u0.z; o0.w = (E0[i].w*bs)*u0.w;
                o1.x = (E1[i].x*bs)*u1.x; o1.y = (E1[i].y*bs)*u1.y;
                o1.z = (E1[i].z*bs)*u1.z; o1.w = (E1[i].w*bs)*u1.w;
                float4* orow = (float4*)(out + (size_t)(rs + lr) * NK);
                orow[lane] = o0;
                orow[32 + lane] = o1;
            }
        }
    }
}

__global__ void __launch_bounds__(BLOCK_P, 1)
sinkhorn_persist(const float* __restrict__ fin, const float* __restrict__ win,
                 float* __restrict__ out) {
    extern __shared__ char smem[];
    double*   sred = (double*)(smem + OFF_RED);
    double*   sK2  = (double*)(smem + OFF_K2);
    double*   sR1  = (double*)(smem + OFF_R1);
    double*   sscl = (double*)(smem + OFF_SCL);
    unsigned* sbar = (unsigned*)(smem + OFF_BARS);
    float*    sw   = (float*) (smem + OFF_W);
    float*    sbuf = (float*) (smem + OFF_BUF);
    float*    sv1  = (float*) (smem + OFF_V1);
    float*    sv2  = (float*) (smem + OFF_V2);
    float*    su   = (float*) (smem + OFF_U);
    float*    sacc = (float*) (smem + OFF_ACC);
    float*    sE   = (float*) (smem + OFF_E);

    const int tid  = threadIdx.x;
    const int lane = tid & 31, warp = tid >> 5;
    const int bid  = blockIdx.x;
    const int rs = (NB * bid) / GRID_P;
    const int re = (NB * (bid + 1)) / GRID_P;
    const int nrows = re - rs;

    // ---- phase A: zero globals (block 0); load w; softmax(w) -> sK2 (all);
    //      stage raw f into smem E area + column-max partials ----
    if (bid == 0 && tid < NK) {
        __stcg(&g_R1[tid * GP], 0.0);
#pragma unroll
        for (int s2 = 0; s2 < 2; s2++) {
            __stcg(&g_R2[s2][tid * GP], 0.0);  __stcg(&g_R3[s2][tid * GP], 0.0);
            __stcg(&g_ub1[s2][tid * GP], 0.0); __stcg(&g_ub2[s2][tid * GP], 0.0);
            __stcg(&g_ub3[s2][tid * GP], 0.0);
        }
    }
    if (tid < NK) { float wv = win[tid]; sw[tid] = wv; sbuf[tid] = 0.f; su[tid] = wv; }
    __syncthreads();
    if (warp == 0) {
        float m = -3.4e38f;
#pragma unroll
        for (int i = 0; i < 8; i++) m = fmaxf(m, su[lane + 32*i]);
        m = warpRedMaxF(m);
        if (lane == 0) sscl[0] = (double)m;
    }
    __syncthreads();
    {   float m = (float)sscl[0];
        float ex = 0.f;
        if (tid < NK) { ex = expf(sw[tid] - m); sred[tid] = (double)ex; }
        __syncthreads();
        if (warp == 0) {
            double s = 0.0;
#pragma unroll
            for (int i = 0; i < 8; i++) s += sred[lane + 32*i];
            s = warpRedSumD(s);
            if (lane == 0) sscl[0] = s;
        }
        __syncthreads();
        float ssum = (float)sscl[0];
        if (tid < NK) sK2[tid] = (double)(ex / ssum);
    }
    {   // stage f into smem + column max (thread = (col, row-quarter))
        int col = tid & 255, q = tid >> 8;
        float mx = -3.4e38f;
        for (int r = rs + q; r < re; r += 4) {
            float f = fin[(size_t)r * NK + col];
            sE[(r - rs) * NK + col] = f;
            mx = fmaxf(mx, f);
        }
        atomicMax(&g_cmax[col * GPC], encf(mx));   // idempotent across replays
    }
    gridBar(sbar, tid, bid);

    // ---- phase B: E' = exp((f-colmax)*20) in place; R1 = colsum ----
    {
        int col = tid & 255, q = tid >> 8;
        float Mt = decf(__ldcg(&g_cmax[col * GPC]));
        float r1p = 0.f;
        for (int r = rs + q; r < re; r += 4) {
            float e = expf((sE[(r - rs) * NK + col] - Mt) * 20.0f);
            sE[(r - rs) * NK + col] = e;
            r1p += e;
        }
        atomicAdd(&g_R1[col * GP], (double)r1p);
    }
    gridBar(sbar, tid, bid);
    if (tid < NK) sR1[tid] = __ldcg(&g_R1[tid * GP]);
    __syncthreads();

    // ---- outer loop ----
    for (int it = 0; it < N_OUTER; ++it) {
        const int s = it & 1;
        const bool last = (it == N_OUTER - 1);

        // fwd1: u1 = K2/R1 -> sv1, R2[s]
        if (tid < NK) su[tid] = __fdividef((float)sK2[tid], (float)sR1[tid]);
        __syncthreads();
        fwdBody(sE, su, sv1, nrows, g_R2[s], sacc, lane, warp, tid);
        gridBar(sbar, tid, bid);

        // zero next iteration's accumulator slot (block 0; double-buffered:
        // slot s^1 was last read before this barrier, next written 2 bars later)
        if (bid == 0 && !last && tid < NK) {
            int t2 = s ^ 1;
            __stcg(&g_R2[t2][tid * GP], 0.0);  __stcg(&g_R3[t2][tid * GP], 0.0);
            __stcg(&g_ub1[t2][tid * GP], 0.0); __stcg(&g_ub2[t2][tid * GP], 0.0);
            __stcg(&g_ub3[t2][tid * GP], 0.0);
        }

        // fwd2: u2 = K2/R2 -> sv2, R3[s]
        if (tid < NK)
            su[tid] = __fdividef((float)sK2[tid], (float)__ldcg(&g_R2[s][tid * GP]));
        __syncthreads();
        fwdBody(sE, su, sv2, nrows, g_R3[s], sacc, lane, warp, tid);
        gridBar(sbar, tid, bid);

        if (!last) {
            // passC: u3 = K2/R3 -> ub3[s]
            if (tid < NK)
                su[tid] = __fdividef((float)sK2[tid], (float)__ldcg(&g_R3[s][tid * GP]));
            __syncthreads();
            passCBody(sE, su, fin, rs, nrows, g_ub3[s], sacc, lane, warp, tid);
            gridBar(sbar, tid, bid);

            // bwd layer 2: rb = -ub3*K2/R3^2 (K-side DP), uses sv2 -> ub2[s]
            if (tid < NK) {
                double R = __ldcg(&g_R3[s][tid * GP]);
                double rd = (double)frcp((float)R);
                su[tid] = (float)((-__ldcg(&g_ub3[s][tid * GP]) * sK2[tid] * rd) * rd);
            }
            __syncthreads();
            bwdBody(sE, su, sv2, nrows, g_ub2[s], sacc, lane, warp, tid);
            gridBar(sbar, tid, bid);

            // bwd layer 1: rb = -ub2*K2/R2^2, uses sv1 -> ub1[s]
            if (tid < NK) {
                double R = __ldcg(&g_R2[s][tid * GP]);
                double rd = (double)frcp((float)R);
                su[tid] = (float)((-__ldcg(&g_ub2[s][tid * GP]) * sK2[tid] * rd) * rd);
            }
            __syncthreads();
            bwdBody(sE, su, sv1, nrows, g_ub1[s], sacc, lane, warp, tid);
            gridBar(sbar, tid, bid);

            // ---- SGD update, redundant per block, warp-reduced ----
            double K2j = 0.0, kb = 0.0;
            if (tid < NK) {
                K2j = sK2[tid];
                kb = __ldcg(&g_ub1[s][tid * GP]) * rcpd(sR1[tid])
                   + __ldcg(&g_ub2[s][tid * GP]) * rcpd(__ldcg(&g_R2[s][tid * GP]))
                   + __ldcg(&g_ub3[s][tid * GP]) * rcpd(__ldcg(&g_R3[s][tid * GP]));
                sred[tid] = kb * K2j;
            }
            __syncthreads();
            if (warp == 0) {
                double d = 0.0;
#pragma unroll
                for (int i = 0; i < 8; i++) d += sred[lane + 32*i];
                d = warpRedSumD(d);
                if (lane == 0) sscl[0] = d;
            }
            __syncthreads();
            double dot = sscl[0];
            float gf = 0.f;
            if (tid < NK) {
                double g = K2j*(kb - dot) + 5.0*(K2j*(1.0/256.0) - (1.0/65536.0));
                gf = (float)g;
                sred[tid] = (double)gf * (double)gf;
            }
            __syncthreads();
            if (warp == 0) {
                double d = 0.0;
#pragma unroll
                for (int i = 0; i < 8; i++) d += sred[lane + 32*i];
                d = warpRedSumD(d);
                if (lane == 0) sscl[0] = sqrt(d);
            }
            __syncthreads();
            float norm = (float)sscl[0];
            if (tid < NK) {
                gf *= fminf(1.0f, 1.0f/(norm + 1e-6f));
                float bf = 0.99f*sbuf[tid] + gf; sbuf[tid] = bf;
                float wv = sw[tid] - 0.1f*bf;    sw[tid]   = wv;
                su[tid] = wv;
            }
            __syncthreads();
            if (warp == 0) {
                float m = -3.4e38f;
#pragma unroll
                for (int i = 0; i < 8; i++) m = fmaxf(m, su[lane + 32*i]);
                m = warpRedMaxF(m);
                if (lane == 0) sscl[0] = (double)m;
            }
            __syncthreads();
            float m = (float)sscl[0];
            float ex = 0.f;
            if (tid < NK) { ex = expf(sw[tid] - m); sred[tid] = (double)ex; }
            __syncthreads();
            if (warp == 0) {
                double d = 0.0;
#pragma unroll
                for (int i = 0; i < 8; i++) d += sred[lane + 32*i];
                d = warpRedSumD(d);
                if (lane == 0) sscl[0] = d;
            }
            __syncthreads();
            float ssum = (float)sscl[0];
            if (tid < NK) sK2[tid] = (double)(ex / ssum);
            __syncthreads();
        } else {
            // final: Q uses pre-update w
            if (tid < NK)
                su[tid] = __fdividef((float)sK2[tid], (float)__ldcg(&g_R3[s][tid * GP]));
            __syncthreads();
            outBody(sE, su, out, rs, nrows, lane, warp);
        }
    }
}

// ---------------------------------------------------------------------------
extern "C" void kernel_launch(void* const* d_in, const int* in_sizes, int n_in,
                              void* d_out, int out_size) {
    const float* fin = nullptr;
    const float* win = nullptr;
    for (int i = 0; i < n_in; i++) {
        if (in_sizes[i] == NB*NK)   fin = (const float*)d_in[i];
        else if (in_sizes[i] == NK) win = (const float*)d_in[i];
    }
    if (!fin) fin = (const float*)d_in[0];
    if (!win) win = (const float*)d_in[1];
    float* out = (float*)d_out;

    cudaFuncSetAttribute(sinkhorn_persist,
                         cudaFuncAttributeMaxDynamicSharedMemorySize, SMEM_TOTAL);
    sinkhorn_persist<<<GRID_P, BLOCK_P, SMEM_TOTAL>>>(fin, win, out);
}